// round 15
// baseline (speedup 1.0000x reference)
#include <cuda_runtime.h>
#include <math.h>

// Problem constants (fixed by reference: R=32, G=32768, N=256, SH_DIM=9)
#define G_TOTAL 32768
#define NPTS    256
#define TPB     128
#define PPB     64    // points per block -> grid 256x4 = 1024 blocks (1 wave)

// SH normalization constants (degree 2, real basis)
#define C0  0.28209479177387814f
#define C1  0.4886025119029199f
#define C2A 0.5462742152960396f
#define C2B 0.15769578262626002f
#define C2C 0.2730689607973162f
#define NL2E (-1.4426950408889634f)   // -log2(e)

__device__ __forceinline__ float rsq_approx(float x) {
    float r; asm("rsqrt.approx.f32 %0, %1;" : "=f"(r) : "f"(x)); return r;
}
__device__ __forceinline__ float ex2_approx(float x) {
    float r; asm("ex2.approx.f32 %0, %1;" : "=f"(r) : "f"(x)); return r;
}
__device__ __forceinline__ float rcp_approx(float x) {
    float r; asm("rcp.approx.f32 %0, %1;" : "=f"(r) : "f"(x)); return r;
}

__global__ __launch_bounds__(TPB) void gausssplat_kernel(
    const float* __restrict__ points,     // [N,3]
    const float* __restrict__ positions,  // [G,3]
    const float* __restrict__ scales,     // [G,3]
    const float4* __restrict__ rotations, // [G] float4 (16B aligned)
    const float* __restrict__ opacity,    // [G]
    const float* __restrict__ sh,         // [G,9]
    float* __restrict__ out)              // [N*G rgb][G sigma]
{
    const int g     = blockIdx.x * TPB + threadIdx.x;   // one gaussian per thread
    const int nbase = blockIdx.y * PPB;

    // Stage point chunk as float4 (pre-scaled by 1/4): one LDS.128 per iter
    __shared__ float4 sp[PPB];
    if (threadIdx.x < PPB) {
        const int n = nbase + threadIdx.x;
        sp[threadIdx.x] = make_float4(points[3*n + 0] * 0.25f,
                                      points[3*n + 1] * 0.25f,
                                      points[3*n + 2] * 0.25f, 0.0f);
    }
    __syncthreads();

    // ---- Per-gaussian precompute (amortized over PPB points) ----
    const float isx = rcp_approx(scales[3*g + 0] + 1e-6f);
    const float isy = rcp_approx(scales[3*g + 1] + 1e-6f);
    const float isz = rcp_approx(scales[3*g + 2] + 1e-6f);

    const float4 qv = rotations[g];    // one LDG.128
    const float q0 = qv.x, q1 = qv.y, q2 = qv.z, q3 = qv.w;

    // M = R * diag(1/s)  (quat->matrix without normalization, as reference)
    const float m00 = (1.0f - 2.0f*(q2*q2 + q3*q3)) * isx;
    const float m01 = (2.0f*(q1*q2 - q0*q3))        * isy;
    const float m02 = (2.0f*(q1*q3 + q0*q2))        * isz;
    const float m10 = (2.0f*(q1*q2 + q0*q3))        * isx;
    const float m11 = (1.0f - 2.0f*(q1*q1 + q3*q3)) * isy;
    const float m12 = (2.0f*(q2*q3 - q0*q1))        * isz;
    const float m20 = (2.0f*(q1*q3 - q0*q2))        * isx;
    const float m21 = (2.0f*(q2*q3 + q0*q1))        * isy;
    const float m22 = (1.0f - 2.0f*(q1*q1 + q2*q2)) * isz;

    const float px = positions[3*g + 0];
    const float py = positions[3*g + 1];
    const float pz = positions[3*g + 2];
    const float ncx = -(m00*px + m01*py + m02*pz);
    const float ncy = -(m10*px + m11*py + m12*pz);
    const float ncz = -(m20*px + m21*py + m22*pz);

    // Fold SH norm constants AND -log2(e) (ex2 sigmoid) into coefficients
    const float s1c = sh[9*g + 1] * (C1 * NL2E);
    const float s2c = sh[9*g + 2] * (C1 * NL2E);
    const float s3c = sh[9*g + 3] * (C1 * NL2E);
    const float s4c = sh[9*g + 4] * (C2A * NL2E);
    const float s5c = sh[9*g + 5] * (C2A * NL2E);
    const float s63 = sh[9*g + 6] * (3.0f * C2B * NL2E);
    const float s7c = sh[9*g + 7] * (C2A * NL2E);
    const float s8c = sh[9*g + 8] * (C2C * NL2E);
    const float bse = (sh[9*g + 0] * C0 - sh[9*g + 6] * C2B) * NL2E;

    // sigma = softplus(opacity) once
    if (blockIdx.y == 0) {
        const float o = opacity[g];
        out[(size_t)NPTS * G_TOTAL + g] =
            fmaxf(o, 0.0f) + log1pf(__expf(-fabsf(o)));
    }

    float* __restrict__ orow = out + (size_t)nbase * G_TOTAL + g;

    #pragma unroll 16
    for (int i = 0; i < PPB; ++i) {
        const float4 p = sp[i];

        // rotated+scaled diff: M*p - c (9 FMA)
        const float rx = fmaf(m00, p.x, fmaf(m01, p.y, fmaf(m02, p.z, ncx)));
        const float ry = fmaf(m10, p.x, fmaf(m11, p.y, fmaf(m12, p.z, ncy)));
        const float rz = fmaf(m20, p.x, fmaf(m21, p.y, fmaf(m22, p.z, ncz)));

        const float zz = rz * rz;
        const float n2 = fmaf(rx, rx, fmaf(ry, ry, zz));
        const float inv = rsq_approx(n2);

        // degree-1 (unnormalized)
        const float lin = fmaf(s1c, ry, fmaf(s2c, rz, s3c * rx));
        // degree-2 (unnormalized, Horner): x(s8x+s4y+s7z) + y(s5z-s8y) + s63 z^2
        const float t1 = fmaf(s8c, rx, fmaf(s4c, ry, s7c * rz));
        const float t2 = fmaf(-s8c, ry, s5c * rz);
        const float q  = fmaf(rx, t1, fmaf(ry, t2, s63 * zz));

        // v' = -log2e*v, nested: (q*inv + lin)*inv + bse
        const float v = fmaf(fmaf(q, inv, lin), inv, bse);
        orow[(size_t)i * G_TOTAL] = rcp_approx(1.0f + ex2_approx(v));
    }
}

extern "C" void kernel_launch(void* const* d_in, const int* in_sizes, int n_in,
                              void* d_out, int out_size) {
    const float* points    = (const float*)d_in[0];
    const float* positions = (const float*)d_in[1];
    const float* scales    = (const float*)d_in[2];
    const float4* rotations= (const float4*)d_in[3];
    const float* opacity   = (const float*)d_in[4];
    const float* sh        = (const float*)d_in[5];
    float* out = (float*)d_out;

    dim3 grid(G_TOTAL / TPB, NPTS / PPB);
    gausssplat_kernel<<<grid, TPB>>>(points, positions, scales, rotations,
                                     opacity, sh, out);
}